// round 3
// baseline (speedup 1.0000x reference)
#include <cuda_runtime.h>
#include <math.h>

#define H 64
#define W 64
#define C 256
#define P 7
#define NUM_ROIS 256

__device__ __forceinline__ float4 fmax4(float4 a, float4 b) {
    a.x = fmaxf(a.x, b.x);
    a.y = fmaxf(a.y, b.y);
    a.z = fmaxf(a.z, b.z);
    a.w = fmaxf(a.w, b.w);
    return a;
}

// One block per (roi, i, j) bin. 64 threads = 64 float4 channel groups (C=256).
// Inner y-loop unrolled 4x with clamped indices (clamp to last valid y — safe
// for max, and the duplicate loads are guaranteed L1 hits).
__global__ __launch_bounds__(64) void roi_pool_kernel(
    const float* __restrict__ feat,   // (H, W, C)
    const float* __restrict__ rois,   // (NUM_ROIS, 4) = x1,y1,x2,y2
    float* __restrict__ out)          // (NUM_ROIS, P, P, C)
{
    const int b  = blockIdx.x;        // r*49 + i*7 + j
    const int r  = b / (P * P);
    const int ij = b - r * (P * P);
    const int i  = ij / P;
    const int j  = ij - i * P;

    const float x1 = __ldg(&rois[r * 4 + 0]);
    const float y1 = __ldg(&rois[r * 4 + 1]);
    const float x2 = __ldg(&rois[r * 4 + 2]);
    const float y2 = __ldg(&rois[r * 4 + 3]);

    // x axis (H) bin bounds — exact reference math
    const int lox   = (int)floorf(x1 * (float)H);
    const int hix   = (int)ceilf(x2 * (float)H);
    const int spanx = max(hix - lox, 1);
    int xs          = lox + (i * spanx) / P;                       // floor
    const int xe    = lox + ((i + 1) * spanx + (P - 1)) / P;       // ceil
    const int xlen  = max(xe - xs, 1);                             // from unclipped
    xs = min(max(xs, 0), H - 1);

    // y axis (W) bin bounds
    const int loy   = (int)floorf(y1 * (float)W);
    const int hiy   = (int)ceilf(y2 * (float)W);
    const int spany = max(hiy - loy, 1);
    int ys          = loy + (j * spany) / P;
    const int ye    = loy + ((j + 1) * spany + (P - 1)) / P;
    const int ylen  = max(ye - ys, 1);
    ys = min(max(ys, 0), W - 1);

    const int c4    = (int)threadIdx.x << 2;   // float4 channel offset
    const int ylast = ylen - 1;

    const float NEG = -INFINITY;
    float4 a0 = make_float4(NEG, NEG, NEG, NEG);
    float4 a1 = a0, a2 = a0, a3 = a0;

    for (int sx = 0; sx < xlen; ++sx) {
        const int x = min(xs + sx, H - 1);
        const float* rowp = feat + (size_t)x * (W * C) + c4;
        for (int sy = 0; sy < ylen; sy += 4) {
            // clamp to last valid y: duplicate loads are L1 hits, max-safe
            const int y0 = min(ys + sy,                 W - 1);
            const int y1i = min(ys + min(sy + 1, ylast), W - 1);
            const int y2i = min(ys + min(sy + 2, ylast), W - 1);
            const int y3i = min(ys + min(sy + 3, ylast), W - 1);
            float4 v0 = *reinterpret_cast<const float4*>(rowp + y0  * C);
            float4 v1 = *reinterpret_cast<const float4*>(rowp + y1i * C);
            float4 v2 = *reinterpret_cast<const float4*>(rowp + y2i * C);
            float4 v3 = *reinterpret_cast<const float4*>(rowp + y3i * C);
            a0 = fmax4(a0, v0);
            a1 = fmax4(a1, v1);
            a2 = fmax4(a2, v2);
            a3 = fmax4(a3, v3);
        }
    }

    a0 = fmax4(fmax4(a0, a1), fmax4(a2, a3));

    float* op = out + ((size_t)b * C) + c4;
    *reinterpret_cast<float4*>(op) = a0;
}

extern "C" void kernel_launch(void* const* d_in, const int* in_sizes, int n_in,
                              void* d_out, int out_size) {
    const float* feat = (const float*)d_in[0];
    const float* rois = (const float*)d_in[1];
    if (n_in >= 2 && in_sizes[0] == NUM_ROIS * 4 && in_sizes[1] == H * W * C) {
        feat = (const float*)d_in[1];
        rois = (const float*)d_in[0];
    }
    float* out = (float*)d_out;

    roi_pool_kernel<<<NUM_ROIS * P * P, 64>>>(feat, rois, out);
}